// round 1
// baseline (speedup 1.0000x reference)
#include <cuda_runtime.h>
#include <math_constants.h>

// Problem constants (fixed by the reference setup)
#define NN    50000
#define EE    1600000
#define DIN   128
#define DOUT  128
#define HH    8
#define DHH   16
#define DGG   64
#define NCOLS 320   // DG + 2*DOUT combined GEMM output cols

// ---------------- device scratch (no allocation allowed) ----------------
__device__ float g_zj[NN * DGG];       // feat @ Wpg            [N,64]
__device__ float g_f0[NN * DOUT];      // relu(feat@W0 + b0)    [N,128]
__device__ float g_f1[NN * DOUT];      // relu(feat@W1 + b1)    [N,128]
__device__ float g_aself[NN * HH];     // leaky(f0 . att_self)  [N,8]
__device__ float g_aneigh[NN * HH];    // leaky(f1 . att_neigh) [N,8]
__device__ int   g_cnt[NN];
__device__ int   g_ptr[NN + 1];
__device__ int   g_pos[NN];
__device__ int   g_perm[EE];

// ---------------- CSR build ----------------
__global__ void k_zero_cnt() {
    int i = blockIdx.x * blockDim.x + threadIdx.x;
    if (i < NN) g_cnt[i] = 0;
}

__global__ void k_hist(const int* __restrict__ row) {
    int i = blockIdx.x * blockDim.x + threadIdx.x;
    if (i < EE) atomicAdd(&g_cnt[row[i]], 1);
}

// single-block 1024-thread exclusive scan over g_cnt -> g_ptr (+ g_pos copy)
__global__ void k_scan() {
    __shared__ int wsum[32];
    __shared__ int s_carry;
    int tid  = threadIdx.x;
    int lane = tid & 31;
    int wid  = tid >> 5;
    if (tid == 0) s_carry = 0;
    __syncthreads();
    for (int base = 0; base < NN; base += 1024) {
        int i = base + tid;
        int x = (i < NN) ? g_cnt[i] : 0;
        int v = x;
        #pragma unroll
        for (int off = 1; off < 32; off <<= 1) {
            int t = __shfl_up_sync(0xffffffffu, v, off);
            if (lane >= off) v += t;
        }
        if (lane == 31) wsum[wid] = v;
        __syncthreads();
        if (wid == 0) {
            int s = wsum[lane];
            #pragma unroll
            for (int off = 1; off < 32; off <<= 1) {
                int t = __shfl_up_sync(0xffffffffu, s, off);
                if (lane >= off) s += t;
            }
            wsum[lane] = s;
        }
        __syncthreads();
        int incl  = v + (wid > 0 ? wsum[wid - 1] : 0);
        int carry = s_carry;
        if (i < NN) {
            int e = carry + incl - x;
            g_ptr[i] = e;
            g_pos[i] = e;
        }
        __syncthreads();
        if (tid == 1023) s_carry = carry + incl;
        __syncthreads();
    }
    if (tid == 0) g_ptr[NN] = s_carry;
}

__global__ void k_scatter(const int* __restrict__ row) {
    int i = blockIdx.x * blockDim.x + threadIdx.x;
    if (i < EE) {
        int p = atomicAdd(&g_pos[row[i]], 1);
        g_perm[p] = i;
    }
}

// ---------------- fused projection GEMM: [N,128] x [128,320] ----------------
// cols 0..63   : zj   (no bias, no relu)
// cols 64..191 : f0 = relu(. + b[0])
// cols 192..319: f1 = relu(. + b[1])
__global__ void k_gemm(const float* __restrict__ feat,
                       const float* __restrict__ Wpg,
                       const float* __restrict__ W,
                       const float* __restrict__ b) {
    __shared__ float As[32][32];
    __shared__ float Bs[32][NCOLS];
    int tid  = threadIdx.x;
    int row0 = blockIdx.x * 32;
    int rg = tid >> 5;   // 0..7 -> 4 rows each
    int ct = tid & 31;   // col thread -> 10 cols stride 32
    float acc[4][10];
    #pragma unroll
    for (int i = 0; i < 4; i++)
        #pragma unroll
        for (int j = 0; j < 10; j++) acc[i][j] = 0.f;

    for (int kc = 0; kc < DIN; kc += 32) {
        for (int idx = tid; idx < 32 * 32; idx += 256) {
            int r = idx >> 5, c = idx & 31;
            int gr = row0 + r;
            As[r][c] = (gr < NN) ? feat[gr * DIN + kc + c] : 0.f;
        }
        for (int idx = tid; idx < 32 * NCOLS; idx += 256) {
            int kk = idx / NCOLS, c = idx - kk * NCOLS;
            int k = kc + kk;
            float w;
            if (c < DGG) {
                w = Wpg[k * DGG + c];
            } else {
                int j  = c - DGG;          // 0..255
                int o  = j >> 7;           // order
                int jj = j & 127;
                int h  = jj >> 4, kb = jj & 15;
                w = W[((o * HH + h) * DIN + k) * DHH + kb];
            }
            Bs[kk][c] = w;
        }
        __syncthreads();
        #pragma unroll
        for (int kk = 0; kk < 32; kk++) {
            float a[4], bb[10];
            #pragma unroll
            for (int i = 0; i < 4; i++) a[i] = As[rg * 4 + i][kk];
            #pragma unroll
            for (int j = 0; j < 10; j++) bb[j] = Bs[kk][ct + 32 * j];
            #pragma unroll
            for (int i = 0; i < 4; i++)
                #pragma unroll
                for (int j = 0; j < 10; j++) acc[i][j] += a[i] * bb[j];
        }
        __syncthreads();
    }
    #pragma unroll
    for (int i = 0; i < 4; i++) {
        int r = row0 + rg * 4 + i;
        if (r >= NN) continue;
        #pragma unroll
        for (int j = 0; j < 10; j++) {
            int c = ct + 32 * j;
            float v = acc[i][j];
            if (c < DGG) {
                g_zj[r * DGG + c] = v;
            } else {
                int jj = c - DGG;               // 0..255
                float o = fmaxf(v + b[jj], 0.f);
                if (jj < DOUT) g_f0[r * DOUT + jj] = o;
                else           g_f1[r * DOUT + (jj - DOUT)] = o;
            }
        }
    }
}

// ---------------- attention scalars ----------------
__device__ __forceinline__ float leaky(float x) {
    return x >= 0.f ? x : 0.2f * x;
}

__global__ void k_att(const float* __restrict__ att) {
    int i = blockIdx.x * blockDim.x + threadIdx.x;
    if (i >= NN * HH) return;
    int n = i >> 3, h = i & 7;
    float s = 0.f, t = 0.f;
    const float* f0p = g_f0 + n * DOUT + h * DHH;
    const float* f1p = g_f1 + n * DOUT + h * DHH;
    const float* ap  = att + h * (2 * DHH);
    #pragma unroll
    for (int k = 0; k < DHH; k++) {
        s += f0p[k] * ap[k];
        t += f1p[k] * ap[DHH + k];
    }
    g_aself[i]  = leaky(s);
    g_aneigh[i] = leaky(t);
}

// ---------------- main per-node kernel: aggregate + gate + norm + out ----------------
__global__ void __launch_bounds__(128, 12)
k_main(const int* __restrict__ col,
       const float* __restrict__ val,
       const float* __restrict__ feat,
       const float* __restrict__ wg,       // [320,8]
       const float* __restrict__ scale,    // [2,128]
       const float* __restrict__ offset,   // [2,128]
       float* __restrict__ out) {
    __shared__ int   sc[128];
    __shared__ float sv[128];
    __shared__ float s_z[DGG];
    __shared__ float s_nm[DOUT];
    __shared__ float wred[4][8];
    __shared__ float s_gate[8];
    __shared__ float red[4][4];
    __shared__ float stats[4];

    int n   = blockIdx.x;
    int j   = threadIdx.x;           // 0..127 feature dim
    int h   = j >> 4;                // head
    int lane = j & 31, wid = j >> 5;

    float aself = g_aself[n * HH + h];
    int e0 = g_ptr[n], e1 = g_ptr[n + 1];
    int deg = e1 - e0;

    float aggj = 0.f, nmj = 0.f, zm = -CUDART_INF_F;

    for (int chunk = e0; chunk < e1; chunk += 128) {
        int m = min(128, e1 - chunk);
        if (j < m) {
            int e = g_perm[chunk + j];
            sc[j] = col[e];
            sv[j] = val[e];
        }
        __syncthreads();
        #pragma unroll 4
        for (int i = 0; i < m; i++) {
            int   c = sc[i];
            float v = sv[i];
            float w = (aself + g_aneigh[c * HH + h]) * v;
            aggj += w * g_f1[c * DOUT + j];
            nmj  += v * feat[c * DIN + j];
            if (j < DGG) zm = fmaxf(zm, g_zj[c * DGG + j]);
        }
        __syncthreads();
    }
    if (j < DGG) s_z[j] = (deg > 0) ? zm : 0.f;
    s_nm[j] = nmj;
    __syncthreads();

    // ---- gate[h] = [feat | zmax | nmean] . wg ----
    float part[8];
    #pragma unroll
    for (int hh = 0; hh < 8; hh++) part[hh] = 0.f;
    {
        float z = feat[n * DIN + j];
        const float* wr = wg + j * 8;
        #pragma unroll
        for (int hh = 0; hh < 8; hh++) part[hh] += z * wr[hh];
    }
    {
        float z = (j < DGG) ? s_z[j] : s_nm[j - DGG];
        const float* wr = wg + (128 + j) * 8;
        #pragma unroll
        for (int hh = 0; hh < 8; hh++) part[hh] += z * wr[hh];
    }
    if (j < DGG) {
        float z = s_nm[DGG + j];
        const float* wr = wg + (256 + j) * 8;
        #pragma unroll
        for (int hh = 0; hh < 8; hh++) part[hh] += z * wr[hh];
    }
    #pragma unroll
    for (int hh = 0; hh < 8; hh++) {
        #pragma unroll
        for (int off = 16; off > 0; off >>= 1)
            part[hh] += __shfl_down_sync(0xffffffffu, part[hh], off);
    }
    if (lane == 0) {
        #pragma unroll
        for (int hh = 0; hh < 8; hh++) wred[wid][hh] = part[hh];
    }
    __syncthreads();
    if (j < 8) s_gate[j] = wred[0][j] + wred[1][j] + wred[2][j] + wred[3][j];
    __syncthreads();

    // ---- norm + output ----
    float h0j = g_f0[n * DOUT + j];
    float h1j = aggj * s_gate[h];

    float s0 = h0j, q0 = h0j * h0j, s1 = h1j, q1 = h1j * h1j;
    #pragma unroll
    for (int off = 16; off > 0; off >>= 1) {
        s0 += __shfl_down_sync(0xffffffffu, s0, off);
        q0 += __shfl_down_sync(0xffffffffu, q0, off);
        s1 += __shfl_down_sync(0xffffffffu, s1, off);
        q1 += __shfl_down_sync(0xffffffffu, q1, off);
    }
    if (lane == 0) {
        red[wid][0] = s0; red[wid][1] = q0; red[wid][2] = s1; red[wid][3] = q1;
    }
    __syncthreads();
    if (j == 0) {
        float S0 = 0, Q0 = 0, S1 = 0, Q1 = 0;
        #pragma unroll
        for (int w = 0; w < 4; w++) {
            S0 += red[w][0]; Q0 += red[w][1]; S1 += red[w][2]; Q1 += red[w][3];
        }
        float mu0 = S0 * (1.f / DOUT);
        float mu1 = S1 * (1.f / DOUT);
        float v0  = Q0 * (1.f / DOUT) - mu0 * mu0 + 1e-9f;
        float v1  = Q1 * (1.f / DOUT) - mu1 * mu1 + 1e-9f;
        stats[0] = mu0; stats[1] = rsqrtf(v0);
        stats[2] = mu1; stats[3] = rsqrtf(v1);
    }
    __syncthreads();

    float o0 = (h0j - stats[0]) * stats[1] * scale[j]        + offset[j];
    float o1 = (h1j - stats[2]) * stats[3] * scale[DOUT + j] + offset[DOUT + j];
    out[n * DOUT + j] = o0 + o1;
}

// ---------------- launch ----------------
extern "C" void kernel_launch(void* const* d_in, const int* in_sizes, int n_in,
                              void* d_out, int out_size) {
    const int*   row    = (const int*)d_in[0];
    const int*   col    = (const int*)d_in[1];
    const float* val    = (const float*)d_in[2];
    const float* feat   = (const float*)d_in[3];
    const float* W      = (const float*)d_in[4];
    const float* b      = (const float*)d_in[5];
    const float* att    = (const float*)d_in[6];
    const float* offset = (const float*)d_in[7];
    const float* scale  = (const float*)d_in[8];
    const float* wg     = (const float*)d_in[9];
    const float* wpg    = (const float*)d_in[10];
    float* out = (float*)d_out;

    // CSR build
    k_zero_cnt<<<(NN + 255) / 256, 256>>>();
    k_hist<<<(EE + 255) / 256, 256>>>(row);
    k_scan<<<1, 1024>>>();
    k_scatter<<<(EE + 255) / 256, 256>>>(row);

    // Dense projections
    k_gemm<<<(NN + 31) / 32, 256>>>(feat, wpg, W, b);
    k_att<<<(NN * HH + 255) / 256, 256>>>(att);

    // Fused aggregate + gate + norm + output
    k_main<<<NN, 128>>>(col, val, feat, wg, scale, offset, out);
}

// round 2
// speedup vs baseline: 1.0040x; 1.0040x over previous
#include <cuda_runtime.h>
#include <math_constants.h>

// Problem constants (fixed by the reference setup)
#define NN    50000
#define EE    1600000
#define DIN   128
#define DOUT  128
#define HH    8
#define DHH   16
#define DGG   64
#define NCOLS 320   // DG + 2*DOUT combined GEMM output cols

// ---------------- device scratch (no allocation allowed) ----------------
__device__ float g_zj[NN * DGG];       // feat @ Wpg            [N,64]
__device__ float g_f0[NN * DOUT];      // relu(feat@W0 + b0)    [N,128]
__device__ float g_f1[NN * DOUT];      // relu(feat@W1 + b1)    [N,128]
__device__ float g_aself[NN * HH];     // leaky(f0 . att_self)  [N,8]
__device__ float g_aneigh[NN * HH];    // leaky(f1 . att_neigh) [N,8]
__device__ int   g_cnt[NN];
__device__ int   g_ptr[NN + 1];
__device__ int   g_pos[NN];
__device__ int   g_perm[EE];

// ---------------- CSR build ----------------
__global__ void k_zero_cnt() {
    int i = blockIdx.x * blockDim.x + threadIdx.x;
    if (i < NN) g_cnt[i] = 0;
}

__global__ void k_hist(const int* __restrict__ row) {
    int i = blockIdx.x * blockDim.x + threadIdx.x;
    if (i < EE) atomicAdd(&g_cnt[row[i]], 1);
}

// single-block 1024-thread exclusive scan over g_cnt -> g_ptr (+ g_pos copy)
__global__ void k_scan() {
    __shared__ int wsum[32];
    __shared__ int s_carry;
    int tid  = threadIdx.x;
    int lane = tid & 31;
    int wid  = tid >> 5;
    if (tid == 0) s_carry = 0;
    __syncthreads();
    for (int base = 0; base < NN; base += 1024) {
        int i = base + tid;
        int x = (i < NN) ? g_cnt[i] : 0;
        int v = x;
        #pragma unroll
        for (int off = 1; off < 32; off <<= 1) {
            int t = __shfl_up_sync(0xffffffffu, v, off);
            if (lane >= off) v += t;
        }
        if (lane == 31) wsum[wid] = v;
        __syncthreads();
        if (wid == 0) {
            int s = wsum[lane];
            #pragma unroll
            for (int off = 1; off < 32; off <<= 1) {
                int t = __shfl_up_sync(0xffffffffu, s, off);
                if (lane >= off) s += t;
            }
            wsum[lane] = s;
        }
        __syncthreads();
        int incl  = v + (wid > 0 ? wsum[wid - 1] : 0);
        int carry = s_carry;
        if (i < NN) {
            int e = carry + incl - x;
            g_ptr[i] = e;
            g_pos[i] = e;
        }
        __syncthreads();
        if (tid == 1023) s_carry = carry + incl;
        __syncthreads();
    }
    if (tid == 0) g_ptr[NN] = s_carry;
}

__global__ void k_scatter(const int* __restrict__ row) {
    int i = blockIdx.x * blockDim.x + threadIdx.x;
    if (i < EE) {
        int p = atomicAdd(&g_pos[row[i]], 1);
        g_perm[p] = i;
    }
}

// ---------------- fused projection GEMM: [N,128] x [128,320] ----------------
// cols 0..63   : zj   (no bias, no relu)
// cols 64..191 : f0 = relu(. + b[0])
// cols 192..319: f1 = relu(. + b[1])
__global__ void k_gemm(const float* __restrict__ feat,
                       const float* __restrict__ Wpg,
                       const float* __restrict__ W,
                       const float* __restrict__ b) {
    __shared__ float As[32][32];
    __shared__ float Bs[32][NCOLS];
    int tid  = threadIdx.x;
    int row0 = blockIdx.x * 32;
    int rg = tid >> 5;   // 0..7 -> 4 rows each
    int ct = tid & 31;   // col thread -> 10 cols stride 32
    float acc[4][10];
    #pragma unroll
    for (int i = 0; i < 4; i++)
        #pragma unroll
        for (int j = 0; j < 10; j++) acc[i][j] = 0.f;

    for (int kc = 0; kc < DIN; kc += 32) {
        for (int idx = tid; idx < 32 * 32; idx += 256) {
            int r = idx >> 5, c = idx & 31;
            int gr = row0 + r;
            As[r][c] = (gr < NN) ? feat[gr * DIN + kc + c] : 0.f;
        }
        for (int idx = tid; idx < 32 * NCOLS; idx += 256) {
            int kk = idx / NCOLS, c = idx - kk * NCOLS;
            int k = kc + kk;
            float w;
            if (c < DGG) {
                w = Wpg[k * DGG + c];
            } else {
                int j  = c - DGG;          // 0..255
                int o  = j >> 7;           // order
                int jj = j & 127;
                int h  = jj >> 4, kb = jj & 15;
                w = W[((o * HH + h) * DIN + k) * DHH + kb];
            }
            Bs[kk][c] = w;
        }
        __syncthreads();
        #pragma unroll
        for (int kk = 0; kk < 32; kk++) {
            float a[4], bb[10];
            #pragma unroll
            for (int i = 0; i < 4; i++) a[i] = As[rg * 4 + i][kk];
            #pragma unroll
            for (int j = 0; j < 10; j++) bb[j] = Bs[kk][ct + 32 * j];
            #pragma unroll
            for (int i = 0; i < 4; i++)
                #pragma unroll
                for (int j = 0; j < 10; j++) acc[i][j] += a[i] * bb[j];
        }
        __syncthreads();
    }
    #pragma unroll
    for (int i = 0; i < 4; i++) {
        int r = row0 + rg * 4 + i;
        if (r >= NN) continue;
        #pragma unroll
        for (int j = 0; j < 10; j++) {
            int c = ct + 32 * j;
            float v = acc[i][j];
            if (c < DGG) {
                g_zj[r * DGG + c] = v;
            } else {
                int jj = c - DGG;               // 0..255
                float o = fmaxf(v + b[jj], 0.f);
                if (jj < DOUT) g_f0[r * DOUT + jj] = o;
                else           g_f1[r * DOUT + (jj - DOUT)] = o;
            }
        }
    }
}

// ---------------- attention scalars ----------------
__device__ __forceinline__ float leaky(float x) {
    return x >= 0.f ? x : 0.2f * x;
}

__global__ void k_att(const float* __restrict__ att) {
    int i = blockIdx.x * blockDim.x + threadIdx.x;
    if (i >= NN * HH) return;
    int n = i >> 3, h = i & 7;
    float s = 0.f, t = 0.f;
    const float* f0p = g_f0 + n * DOUT + h * DHH;
    const float* f1p = g_f1 + n * DOUT + h * DHH;
    const float* ap  = att + h * (2 * DHH);
    #pragma unroll
    for (int k = 0; k < DHH; k++) {
        s += f0p[k] * ap[k];
        t += f1p[k] * ap[DHH + k];
    }
    g_aself[i]  = leaky(s);
    g_aneigh[i] = leaky(t);
}

// ---------------- main per-node kernel: aggregate + gate + norm + out ----------------
__global__ void __launch_bounds__(128, 12)
k_main(const int* __restrict__ col,
       const float* __restrict__ val,
       const float* __restrict__ feat,
       const float* __restrict__ wg,       // [320,8]
       const float* __restrict__ scale,    // [2,128]
       const float* __restrict__ offset,   // [2,128]
       float* __restrict__ out) {
    __shared__ int   sc[128];
    __shared__ float sv[128];
    __shared__ float s_z[DGG];
    __shared__ float s_nm[DOUT];
    __shared__ float wred[4][8];
    __shared__ float s_gate[8];
    __shared__ float red[4][4];
    __shared__ float stats[4];

    int n   = blockIdx.x;
    int j   = threadIdx.x;           // 0..127 feature dim
    int h   = j >> 4;                // head
    int lane = j & 31, wid = j >> 5;

    float aself = g_aself[n * HH + h];
    int e0 = g_ptr[n], e1 = g_ptr[n + 1];
    int deg = e1 - e0;

    float aggj = 0.f, nmj = 0.f, zm = -CUDART_INF_F;

    for (int chunk = e0; chunk < e1; chunk += 128) {
        int m = min(128, e1 - chunk);
        if (j < m) {
            int e = g_perm[chunk + j];
            sc[j] = col[e];
            sv[j] = val[e];
        }
        __syncthreads();
        #pragma unroll 4
        for (int i = 0; i < m; i++) {
            int   c = sc[i];
            float v = sv[i];
            float w = (aself + g_aneigh[c * HH + h]) * v;
            aggj += w * g_f1[c * DOUT + j];
            nmj  += v * feat[c * DIN + j];
            if (j < DGG) zm = fmaxf(zm, g_zj[c * DGG + j]);
        }
        __syncthreads();
    }
    if (j < DGG) s_z[j] = (deg > 0) ? zm : 0.f;
    s_nm[j] = nmj;
    __syncthreads();

    // ---- gate[h] = [feat | zmax | nmean] . wg ----
    float part[8];
    #pragma unroll
    for (int hh = 0; hh < 8; hh++) part[hh] = 0.f;
    {
        float z = feat[n * DIN + j];
        const float* wr = wg + j * 8;
        #pragma unroll
        for (int hh = 0; hh < 8; hh++) part[hh] += z * wr[hh];
    }
    {
        float z = (j < DGG) ? s_z[j] : s_nm[j - DGG];
        const float* wr = wg + (128 + j) * 8;
        #pragma unroll
        for (int hh = 0; hh < 8; hh++) part[hh] += z * wr[hh];
    }
    if (j < DGG) {
        float z = s_nm[DGG + j];
        const float* wr = wg + (256 + j) * 8;
        #pragma unroll
        for (int hh = 0; hh < 8; hh++) part[hh] += z * wr[hh];
    }
    #pragma unroll
    for (int hh = 0; hh < 8; hh++) {
        #pragma unroll
        for (int off = 16; off > 0; off >>= 1)
            part[hh] += __shfl_down_sync(0xffffffffu, part[hh], off);
    }
    if (lane == 0) {
        #pragma unroll
        for (int hh = 0; hh < 8; hh++) wred[wid][hh] = part[hh];
    }
    __syncthreads();
    if (j < 8) s_gate[j] = wred[0][j] + wred[1][j] + wred[2][j] + wred[3][j];
    __syncthreads();

    // ---- norm + output ----
    float h0j = g_f0[n * DOUT + j];
    float h1j = aggj * s_gate[h];

    float s0 = h0j, q0 = h0j * h0j, s1 = h1j, q1 = h1j * h1j;
    #pragma unroll
    for (int off = 16; off > 0; off >>= 1) {
        s0 += __shfl_down_sync(0xffffffffu, s0, off);
        q0 += __shfl_down_sync(0xffffffffu, q0, off);
        s1 += __shfl_down_sync(0xffffffffu, s1, off);
        q1 += __shfl_down_sync(0xffffffffu, q1, off);
    }
    if (lane == 0) {
        red[wid][0] = s0; red[wid][1] = q0; red[wid][2] = s1; red[wid][3] = q1;
    }
    __syncthreads();
    if (j == 0) {
        float S0 = 0, Q0 = 0, S1 = 0, Q1 = 0;
        #pragma unroll
        for (int w = 0; w < 4; w++) {
            S0 += red[w][0]; Q0 += red[w][1]; S1 += red[w][2]; Q1 += red[w][3];
        }
        float mu0 = S0 * (1.f / DOUT);
        float mu1 = S1 * (1.f / DOUT);
        float v0  = Q0 * (1.f / DOUT) - mu0 * mu0 + 1e-9f;
        float v1  = Q1 * (1.f / DOUT) - mu1 * mu1 + 1e-9f;
        stats[0] = mu0; stats[1] = rsqrtf(v0);
        stats[2] = mu1; stats[3] = rsqrtf(v1);
    }
    __syncthreads();

    float o0 = (h0j - stats[0]) * stats[1] * scale[j]        + offset[j];
    float o1 = (h1j - stats[2]) * stats[3] * scale[DOUT + j] + offset[DOUT + j];
    out[n * DOUT + j] = o0 + o1;
}

// ---------------- launch ----------------
extern "C" void kernel_launch(void* const* d_in, const int* in_sizes, int n_in,
                              void* d_out, int out_size) {
    const int*   row    = (const int*)d_in[0];
    const int*   col    = (const int*)d_in[1];
    const float* val    = (const float*)d_in[2];
    const float* feat   = (const float*)d_in[3];
    const float* W      = (const float*)d_in[4];
    const float* b      = (const float*)d_in[5];
    const float* att    = (const float*)d_in[6];
    const float* offset = (const float*)d_in[7];
    const float* scale  = (const float*)d_in[8];
    const float* wg     = (const float*)d_in[9];
    const float* wpg    = (const float*)d_in[10];
    float* out = (float*)d_out;

    // CSR build
    k_zero_cnt<<<(NN + 255) / 256, 256>>>();
    k_hist<<<(EE + 255) / 256, 256>>>(row);
    k_scan<<<1, 1024>>>();
    k_scatter<<<(EE + 255) / 256, 256>>>(row);

    // Dense projections
    k_gemm<<<(NN + 31) / 32, 256>>>(feat, wpg, W, b);
    k_att<<<(NN * HH + 255) / 256, 256>>>(att);

    // Fused aggregate + gate + norm + output
    k_main<<<NN, 128>>>(col, val, feat, wg, scale, offset, out);
}